// round 9
// baseline (speedup 1.0000x reference)
#include <cuda_runtime.h>
#include <cstdint>

#define D    64
#define BM   128
#define BN   128
#define PAD  68          // words; 68 mod 32 == 4 -> conflict-free fragment LDS
#define NTILES   4096    // 64 x 64 grid of 128x128 tiles
#define TPR      64      // tiles per row
#define GRIDSZ   148

#define TF32_MASK 0xFFFFE000u

__device__ __forceinline__ uint32_t smem_u32(const void* p) {
    uint32_t a;
    asm("{ .reg .u64 t; cvta.to.shared.u64 t, %1; cvt.u32.u64 %0, t; }" : "=r"(a) : "l"(p));
    return a;
}
#define CP_ASYNC16(dst_u32, src_ptr) \
    asm volatile("cp.async.cg.shared.global [%0], [%1], 16;" \
                 :: "r"(dst_u32), "l"(src_ptr) : "memory")
#define CP_COMMIT()  asm volatile("cp.async.commit_group;" ::: "memory")
#define CP_WAIT0()   asm volatile("cp.async.wait_group 0;" ::: "memory")
#define CP_WAIT1()   asm volatile("cp.async.wait_group 1;" ::: "memory")

// ---------------------------------------------------------------------------
// Persistent fused kernel. Each CTA loops over tiles (stride gridDim.x) with
// double-buffered cp.async staging of raw f32 tiles (HMMA tf32 truncates the
// low 13 mantissa bits in HW; norms use the same masked values so
// d2 == ||x~-y~||^2 stays self-consistent).
// Compute core: 8 warps (2x4), warp tile 64x32, mma.sync m16n8k8 tf32.
// ---------------------------------------------------------------------------
__global__ __launch_bounds__(256, 1)
void dist_kernel(const float* __restrict__ x1, const float* __restrict__ x2,
                 float* __restrict__ out, int M) {
    extern __shared__ uint32_t smem[];
    // buffer p: A at smem + p*2*BM*PAD, B right after
    float* snrm = (float*)(smem + 4 * BM * PAD);   // [256]: A norms, B norms

    const int tid  = threadIdx.x;
    const int wid  = tid >> 5;
    const int lane = tid & 31;
    const int wm = wid >> 2;          // 0..1 : 64-row band
    const int wn = wid & 3;           // 0..3 : 32-col band
    const int g  = lane >> 2;         // 0..7
    const int q  = lane & 3;          // 0..3

    const uint32_t sbase = smem_u32(smem);

    // staging decomposition (fixed per thread)
    const int st_r  = tid >> 4;          // row 0..15 (+16 per iter)
    const int st_c4 = (tid & 15) * 4;    // word column

    // ---- prologue: stage tile for this CTA's first index ----
    {
        const int t0 = blockIdx.x;
        const int n0 = (t0 >> 6) * BM, m0 = (t0 & 63) * BN;
        const uint32_t sA = sbase;
        const uint32_t sB = sbase + BM * PAD * 4;
#pragma unroll
        for (int it = 0; it < 8; ++it) {
            int r = st_r + it * 16;
            uint32_t off = (uint32_t)(r * PAD + st_c4) * 4;
            CP_ASYNC16(sA + off, x1 + (size_t)(n0 + r) * D + st_c4);
            CP_ASYNC16(sB + off, x2 + (size_t)(m0 + r) * D + st_c4);
        }
        CP_COMMIT();
    }

    int i = 0;
    for (int t = blockIdx.x; t < NTILES; t += GRIDSZ, ++i) {
        const uint32_t curA = sbase + (uint32_t)((i & 1) * 2 * BM * PAD) * 4;
        const uint32_t curB = curA + BM * PAD * 4;
        const int nt = t + GRIDSZ;

        // ---- issue prefetch of next tile into the other buffer ----
        if (nt < NTILES) {
            const int n0 = (nt >> 6) * BM, m0 = (nt & 63) * BN;
            const uint32_t nA = sbase + (uint32_t)(((i + 1) & 1) * 2 * BM * PAD) * 4;
            const uint32_t nB = nA + BM * PAD * 4;
#pragma unroll
            for (int it = 0; it < 8; ++it) {
                int r = st_r + it * 16;
                uint32_t off = (uint32_t)(r * PAD + st_c4) * 4;
                CP_ASYNC16(nA + off, x1 + (size_t)(n0 + r) * D + st_c4);
                CP_ASYNC16(nB + off, x2 + (size_t)(m0 + r) * D + st_c4);
            }
            CP_COMMIT();
            CP_WAIT1();          // current tile's group complete; next may fly
        } else {
            CP_WAIT0();
        }
        __syncthreads();

        const uint32_t* sa = (const uint32_t*)(smem) + (i & 1) * 2 * BM * PAD;
        const uint32_t* sb = sa + BM * PAD;

        // ---- norms from masked (tf32-effective) values ----
        {
            const uint32_t* rowp = (tid < BM ? sa + tid * PAD
                                             : sb + (tid - BM) * PAD);
            float s = 0.f;
#pragma unroll
            for (int k4 = 0; k4 < 16; ++k4) {
                uint4 u = *(const uint4*)(rowp + k4 * 4);
                float a = __uint_as_float(u.x & TF32_MASK);
                float b = __uint_as_float(u.y & TF32_MASK);
                float c = __uint_as_float(u.z & TF32_MASK);
                float d = __uint_as_float(u.w & TF32_MASK);
                s = fmaf(a, a, s); s = fmaf(b, b, s);
                s = fmaf(c, c, s); s = fmaf(d, d, s);
            }
            snrm[tid] = s;
        }

        float acc[4][4][4];
#pragma unroll
        for (int a_ = 0; a_ < 4; ++a_)
#pragma unroll
            for (int b_ = 0; b_ < 4; ++b_)
#pragma unroll
                for (int c_ = 0; c_ < 4; ++c_) acc[a_][b_][c_] = 0.f;

        __syncthreads();

        // ---- K loop: 8 steps of k=8 (raw f32 bits; HMMA truncates) ----
#pragma unroll
        for (int ks = 0; ks < 8; ++ks) {
            const int kb = ks * 8;
            uint32_t bfr[4][2];
#pragma unroll
            for (int nf = 0; nf < 4; ++nf) {
                const uint32_t* bp = sb + (wn * 32 + nf * 8 + g) * PAD + kb + q;
                bfr[nf][0] = bp[0];
                bfr[nf][1] = bp[4];
            }
#pragma unroll
            for (int mf = 0; mf < 4; ++mf) {
                const int r = wm * 64 + mf * 16 + g;
                const uint32_t* ap = sa + r * PAD + kb + q;
                uint32_t a0 = ap[0];
                uint32_t a1 = ap[8 * PAD];
                uint32_t a2 = ap[4];
                uint32_t a3 = ap[8 * PAD + 4];
#pragma unroll
                for (int nf = 0; nf < 4; ++nf) {
                    asm volatile(
                        "mma.sync.aligned.m16n8k8.row.col.f32.tf32.tf32.f32 "
                        "{%0,%1,%2,%3}, {%4,%5,%6,%7}, {%8,%9}, {%0,%1,%2,%3};"
                        : "+f"(acc[mf][nf][0]), "+f"(acc[mf][nf][1]),
                          "+f"(acc[mf][nf][2]), "+f"(acc[mf][nf][3])
                        : "r"(a0), "r"(a1), "r"(a2), "r"(a3),
                          "r"(bfr[nf][0]), "r"(bfr[nf][1]));
                }
            }
        }

        // ---- epilogue ----
        {
            const int n0 = (t >> 6) * BM, m0 = (t & 63) * BN;
            const float* nrmA = snrm;
            const float* nrmB = snrm + BM;
#pragma unroll
            for (int mf = 0; mf < 4; ++mf) {
                const int rloc = wm * 64 + mf * 16 + g;
                const float s1a = nrmA[rloc];
                const float s1b = nrmA[rloc + 8];
                float* orow_a = out + (size_t)(n0 + rloc) * M + m0;
                float* orow_b = orow_a + (size_t)8 * M;
#pragma unroll
                for (int nf = 0; nf < 4; ++nf) {
                    const int cidx = wn * 32 + nf * 8 + q * 2;
                    const float2 s2 = *(const float2*)&nrmB[cidx];
                    float2 ra, rb;
                    ra.x = fmaxf(fmaf(-2.f, acc[mf][nf][0], s1a + s2.x), 0.f);
                    ra.y = fmaxf(fmaf(-2.f, acc[mf][nf][1], s1a + s2.y), 0.f);
                    rb.x = fmaxf(fmaf(-2.f, acc[mf][nf][2], s1b + s2.x), 0.f);
                    rb.y = fmaxf(fmaf(-2.f, acc[mf][nf][3], s1b + s2.y), 0.f);
                    __stcs((float2*)(orow_a + cidx), ra);
                    __stcs((float2*)(orow_b + cidx), rb);
                }
            }
        }
        __syncthreads();   // protect cur buffer before it becomes prefetch target
    }
}

// ---------------------------------------------------------------------------
extern "C" void kernel_launch(void* const* d_in, const int* in_sizes, int n_in,
                              void* d_out, int out_size) {
    const float* x1 = (const float*)d_in[0];
    const float* x2 = (const float*)d_in[1];
    float* out = (float*)d_out;

    const int M = in_sizes[1] / D;   // 8192

    const int smem_bytes = 4 * BM * PAD * sizeof(uint32_t) + 256 * sizeof(float);
    cudaFuncSetAttribute(dist_kernel,
                         cudaFuncAttributeMaxDynamicSharedMemorySize, smem_bytes);

    dist_kernel<<<GRIDSZ, 256, smem_bytes>>>(x1, x2, out, M);
}